// round 1
// baseline (speedup 1.0000x reference)
#include <cuda_runtime.h>
#include <math.h>

// Problem constants
constexpr int cB = 16;
constexpr int cN = 32;
constexpr int cX = 36;
constexpr int cD = 2048;
constexpr int cH = 512;
constexpr int ROWS = cB * cN;     // 512
constexpr int K2 = 2 * cD;        // 4096
constexpr int NSPLIT = 4;         // K-split for MLP GEMMs
#define BIG_NEG_F (-1000000000.0f)

// ---------------- scratch (device globals; no allocation allowed) ----------------
__device__ float g_X1[ROWS * K2];                 // concat(fc_target, fc_distr)  8MB
__device__ float g_X2[ROWS * K2];                 // concat(target_feats, distr_feats) 8MB
__device__ float g_Hpart[NSPLIT * ROWS * cH];     // MLP hidden partials 4MB
__device__ float g_tproj[cB * cX * cD];           // att_target @ Wbil 4.5MB
__device__ float g_inners[cB * cX * cN * cX];     // [b][x][i*36+y] 2.65MB
__device__ float g_scores[ROWS];

// ---------------- build concat(fc_target bcast, fc_distr) ----------------
__global__ void build_concat(const float* __restrict__ ft, const float* __restrict__ fd,
                             float* __restrict__ X1) {
    long idx = (long)blockIdx.x * blockDim.x + threadIdx.x;
    if (idx >= (long)ROWS * K2) return;
    int row = (int)(idx >> 12);          // / 4096
    int k = (int)(idx & (K2 - 1));
    int b = row >> 5;                    // / 32
    X1[idx] = (k < cD) ? ft[(long)b * cD + k] : fd[(long)row * cD + (k - cD)];
}

// ---------------- generic fp32 GEMM: C[M,N] = A[M,K] @ B ----------------
// NT=false: B is [K,N] row-major. NT=true: B is [N,K] row-major (C = A @ B^T).
// BM=BN=64, BK=16, 256 threads, 4x4 per-thread microtile.
// blockIdx.z: batch (or K-split) with element strides sA/sB/sC.
// N must be a multiple of 64 and of 4; K multiple of 16; M guarded.
template <bool NT>
__global__ void gemm64(const float* __restrict__ A, const float* __restrict__ B,
                       float* __restrict__ C,
                       int M, int N, int Kloop, int lda, int ldb,
                       long sA, long sB, long sC) {
    A += (long)blockIdx.z * sA;
    B += (long)blockIdx.z * sB;
    C += (long)blockIdx.z * sC;
    const int rowBase = blockIdx.y * 64;
    const int colBase = blockIdx.x * 64;

    __shared__ float As[16][68];
    __shared__ float Bs[16][68];

    const int tid = threadIdx.x;
    const int tx = tid & 15;
    const int ty = tid >> 4;

    float acc[4][4];
#pragma unroll
    for (int i = 0; i < 4; i++)
#pragma unroll
        for (int j = 0; j < 4; j++) acc[i][j] = 0.f;

    for (int k0 = 0; k0 < Kloop; k0 += 16) {
        // ---- load A tile (64 x 16), transpose into As[k][m] ----
        {
            int r = tid >> 2;   // 0..63
            int kq = tid & 3;   // 0..3
            int row = rowBase + r;
            float4 v = make_float4(0.f, 0.f, 0.f, 0.f);
            if (row < M) v = *(const float4*)(A + (long)row * lda + k0 + kq * 4);
            As[kq * 4 + 0][r] = v.x;
            As[kq * 4 + 1][r] = v.y;
            As[kq * 4 + 2][r] = v.z;
            As[kq * 4 + 3][r] = v.w;
        }
        // ---- load B tile ----
        if (NT) {
            int r = tid >> 2;   // column of C (row of B')
            int kq = tid & 3;
            float4 v = *(const float4*)(B + (long)(colBase + r) * ldb + k0 + kq * 4);
            Bs[kq * 4 + 0][r] = v.x;
            Bs[kq * 4 + 1][r] = v.y;
            Bs[kq * 4 + 2][r] = v.z;
            Bs[kq * 4 + 3][r] = v.w;
        } else {
            int kr = tid >> 4;  // 0..15
            int nq = tid & 15;  // 0..15
            float4 v = *(const float4*)(B + (long)(k0 + kr) * ldb + colBase + nq * 4);
            *(float4*)&Bs[kr][nq * 4] = v;
        }
        __syncthreads();

#pragma unroll
        for (int k = 0; k < 16; k++) {
            float4 a = *(const float4*)&As[k][ty * 4];
            float4 bv = *(const float4*)&Bs[k][tx * 4];
            float av[4] = {a.x, a.y, a.z, a.w};
            float bw[4] = {bv.x, bv.y, bv.z, bv.w};
#pragma unroll
            for (int i = 0; i < 4; i++)
#pragma unroll
                for (int j = 0; j < 4; j++) acc[i][j] += av[i] * bw[j];
        }
        __syncthreads();
    }

#pragma unroll
    for (int i = 0; i < 4; i++) {
        int row = rowBase + ty * 4 + i;
        if (row < M) {
            float4 o = make_float4(acc[i][0], acc[i][1], acc[i][2], acc[i][3]);
            *(float4*)(C + (long)row * N + colBase + tx * 4) = o;
        }
    }
}

// ---------------- MLP tail: sum K-split partials, +b1, relu, dot W2, +b2 ----------------
__global__ void mlp_reduce(const float* __restrict__ Hp, const float* __restrict__ b1,
                           const float* __restrict__ W2, const float* __restrict__ b2,
                           float* __restrict__ scores, int accumulate) {
    int row = blockIdx.x;
    int tid = threadIdx.x;  // 256
    float s = 0.f;
    for (int j = tid; j < cH; j += 256) {
        float h = b1[j];
#pragma unroll
        for (int p = 0; p < NSPLIT; p++) h += Hp[(long)p * ROWS * cH + (long)row * cH + j];
        h = fmaxf(h, 0.f);
        s += h * W2[j];
    }
    __shared__ float red[256];
    red[tid] = s;
    __syncthreads();
    for (int o = 128; o > 0; o >>= 1) {
        if (tid < o) red[tid] += red[tid + o];
        __syncthreads();
    }
    if (tid == 0) {
        float v = red[0] + b2[0];
        if (accumulate) scores[row] += v;
        else scores[row] = v;
    }
}

// ---------------- attention pooling per (b,i) ----------------
__global__ void attn_kernel(const float* __restrict__ inners,
                            const int* __restrict__ mt, const int* __restrict__ md,
                            const float* __restrict__ att_t, const float* __restrict__ att_d,
                            float* __restrict__ X2) {
    int bi = blockIdx.x;
    int b = bi >> 5;
    int i = bi & 31;
    __shared__ float S[cX][cX];
    __shared__ float tw[cX], dw[cX];
    int tid = threadIdx.x;  // 256

    for (int idx = tid; idx < cX * cX; idx += 256) {
        int x = idx / cX, y = idx % cX;
        float v = inners[((long)b * cX + x) * (cN * cX) + i * cX + y];
        int mm = mt[b * cX + x] * md[(b * cN + i) * cX + y];
        S[x][y] = (mm > 0) ? v : BIG_NEG_F;
    }
    __syncthreads();

    if (tid < cX) {
        float mx = -3.4e38f;
        for (int y = 0; y < cX; y++) mx = fmaxf(mx, S[tid][y]);
        tw[tid] = mx;
    } else if (tid < 2 * cX) {
        int y = tid - cX;
        float mx = -3.4e38f;
        for (int x = 0; x < cX; x++) mx = fmaxf(mx, S[x][y]);
        dw[y] = mx;
    }
    __syncthreads();

    if (tid == 0) {
        float m = -3.4e38f;
        for (int x = 0; x < cX; x++) m = fmaxf(m, tw[x]);
        float s = 0.f;
        for (int x = 0; x < cX; x++) { float e = expf(tw[x] - m); tw[x] = e; s += e; }
        float inv = 1.f / s;
        for (int x = 0; x < cX; x++) tw[x] *= inv;
    }
    if (tid == 32) {
        float m = -3.4e38f;
        for (int y = 0; y < cX; y++) m = fmaxf(m, dw[y]);
        float s = 0.f;
        for (int y = 0; y < cX; y++) { float e = expf(dw[y] - m); dw[y] = e; s += e; }
        float inv = 1.f / s;
        for (int y = 0; y < cX; y++) dw[y] *= inv;
    }
    __syncthreads();

    const float* tb = att_t + (long)b * cX * cD;
    const float* db = att_d + (long)(b * cN + i) * cX * cD;
    for (int d = tid; d < cD; d += 256) {
        float tf = 0.f, df = 0.f;
#pragma unroll
        for (int x = 0; x < cX; x++) {
            tf += tw[x] * tb[(long)x * cD + d];
            df += dw[x] * db[(long)x * cD + d];
        }
        X2[(long)bi * K2 + d] = tf;
        X2[(long)bi * K2 + cD + d] = df;
    }
}

// ---------------- final log_softmax over N=32 ----------------
__global__ void logsoftmax_kernel(const float* __restrict__ scores, float* __restrict__ out) {
    int b = blockIdx.x;
    int n = threadIdx.x;  // 32
    float v = scores[b * cN + n];
    float m = v;
    for (int o = 16; o > 0; o >>= 1) m = fmaxf(m, __shfl_xor_sync(0xffffffffu, m, o));
    float e = expf(v - m);
    float s = e;
    for (int o = 16; o > 0; o >>= 1) s += __shfl_xor_sync(0xffffffffu, s, o);
    out[b * cN + n] = v - m - logf(s);
}

// ---------------- host ----------------
extern "C" void kernel_launch(void* const* d_in, const int* in_sizes, int n_in,
                              void* d_out, int out_size) {
    const float* fc_t = (const float*)d_in[0];
    const float* fc_d = (const float*)d_in[1];
    const float* att_t = (const float*)d_in[2];
    const float* att_d = (const float*)d_in[3];
    const int* am_t = (const int*)d_in[4];
    const int* am_d = (const int*)d_in[5];
    const float* W1 = (const float*)d_in[6];
    const float* b1 = (const float*)d_in[7];
    const float* W2 = (const float*)d_in[8];
    const float* b2 = (const float*)d_in[9];
    const float* Wbil = (const float*)d_in[10];
    const float* oW1 = (const float*)d_in[11];
    const float* ob1 = (const float*)d_in[12];
    const float* oW2 = (const float*)d_in[13];
    const float* ob2 = (const float*)d_in[14];
    float* out = (float*)d_out;

    float *X1, *X2, *Hp, *tproj, *inn, *scores;
    cudaGetSymbolAddress((void**)&X1, g_X1);
    cudaGetSymbolAddress((void**)&X2, g_X2);
    cudaGetSymbolAddress((void**)&Hp, g_Hpart);
    cudaGetSymbolAddress((void**)&tproj, g_tproj);
    cudaGetSymbolAddress((void**)&inn, g_inners);
    cudaGetSymbolAddress((void**)&scores, g_scores);

    // 1) base scorer input
    build_concat<<<(ROWS * K2 + 255) / 256, 256>>>(fc_t, fc_d, X1);

    // 2) base MLP hidden: [512,4096] @ W1[4096,512], K-split x4
    gemm64<false><<<dim3(cH / 64, ROWS / 64, NSPLIT), 256>>>(
        X1, W1, Hp, ROWS, cH, K2 / NSPLIT, K2, cH,
        (long)(K2 / NSPLIT), (long)(K2 / NSPLIT) * cH, (long)ROWS * cH);
    mlp_reduce<<<ROWS, 256>>>(Hp, b1, W2, b2, scores, 0);

    // 3) tproj = att_target_flat[576,2048] @ Wbil[2048,2048]
    gemm64<false><<<dim3(cD / 64, (cB * cX) / 64, 1), 256>>>(
        att_t, Wbil, tproj, cB * cX, cD, cD, cD, cD, 0, 0, 0);

    // 4) inners per b: tproj[b][36,2048] @ att_distr[b][1152,2048]^T -> [36,1152]
    gemm64<true><<<dim3((cN * cX) / 64, 1, cB), 256>>>(
        tproj, att_d, inn, cX, cN * cX, cD, cD, cD,
        (long)cX * cD, (long)cN * cX * cD, (long)cX * cN * cX);

    // 5) masked max/softmax attention pooling -> cat_att
    attn_kernel<<<ROWS, 256>>>(inn, am_t, am_d, att_t, att_d, X2);

    // 6) object MLP (accumulate into scores)
    gemm64<false><<<dim3(cH / 64, ROWS / 64, NSPLIT), 256>>>(
        X2, oW1, Hp, ROWS, cH, K2 / NSPLIT, K2, cH,
        (long)(K2 / NSPLIT), (long)(K2 / NSPLIT) * cH, (long)ROWS * cH);
    mlp_reduce<<<ROWS, 256>>>(Hp, ob1, oW2, ob2, scores, 1);

    // 7) log_softmax over distractors
    logsoftmax_kernel<<<cB, 32>>>(scores, out);
}